// round 4
// baseline (speedup 1.0000x reference)
#include <cuda_runtime.h>
#include <cuda_bf16.h>
#include <stdint.h>

#define Bc 32
#define Sc 128
#define Hc 128
#define BSH (Bc * Sc * Hc)
#define RS 136                 // padded row stride (ushorts) -> conflict-free LDS
#define PLANE 34816            // 128 * 136 * 2 bytes
#define TILE  69632            // hi plane + lo plane
#define NJ 8

// Global scratch (no cudaMalloc allowed)
__device__ __align__(16) uint8_t g_A[256][TILE];  // 2 scales x 128 j: W1'[t][s] hi/lo bf16
__device__ __align__(16) uint8_t g_B[32][TILE];   // per b: X'[h][s] hi/lo bf16
__device__ float g_M[BSH];
__device__ float g_T[BSH];

// ---------------------------------------------------------------------------
__device__ __forceinline__ float gelu_f(float x) {
    return 0.5f * x * (1.0f + erff(x * 0.7071067811865476f));
}
__device__ __forceinline__ unsigned long long dup2(float x) {
    unsigned long long r; unsigned int u = __float_as_uint(x);
    asm("mov.b64 %0, {%1, %1};" : "=l"(r) : "r"(u)); return r;
}
__device__ __forceinline__ void fma2(unsigned long long &d, unsigned long long a,
                                     unsigned long long b) {
    asm("fma.rn.f32x2 %0, %1, %2, %3;" : "=l"(d) : "l"(a), "l"(b), "l"(d));
}
__device__ __forceinline__ float lo32(unsigned long long v) {
    return __uint_as_float((unsigned int)v);
}
__device__ __forceinline__ float hi32(unsigned long long v) {
    return __uint_as_float((unsigned int)(v >> 32));
}
__device__ __forceinline__ uint32_t s2u(const void* p) {
    uint32_t a;
    asm("{ .reg .u64 t; cvta.to.shared.u64 t, %1; cvt.u32.u64 %0, t; }" : "=r"(a) : "l"(p));
    return a;
}
__device__ __forceinline__ void mbar_init(uint32_t a, uint32_t c) {
    asm volatile("mbarrier.init.shared.b64 [%0], %1;" :: "r"(a), "r"(c) : "memory");
}
__device__ __forceinline__ void mbar_expect(uint32_t a, uint32_t bytes) {
    asm volatile("mbarrier.arrive.expect_tx.shared.b64 _, [%0], %1;"
                 :: "r"(a), "r"(bytes) : "memory");
}
__device__ __forceinline__ void mbar_wait(uint32_t a, uint32_t ph) {
    uint32_t done = 0;
    while (!done)
        asm volatile(
            "{\n\t.reg .pred p;\n\t"
            "mbarrier.try_wait.parity.acquire.cta.shared::cta.b64 p, [%1], %2, 0x989680;\n\t"
            "selp.b32 %0, 1, 0, p;\n\t}"
            : "=r"(done) : "r"(a), "r"(ph) : "memory");
}
__device__ __forceinline__ void bulk_g2s(uint32_t dst, const void* src,
                                         uint32_t bytes, uint32_t mbar) {
    asm volatile(
        "cp.async.bulk.shared::cta.global.mbarrier::complete_tx::bytes [%0], [%1], %2, [%3];"
        :: "r"(dst), "l"(src), "r"(bytes), "r"(mbar) : "memory");
}
// bf16 HMMA: D(16x8,f32) += A(16x16,row) * B(16x8,col)
__device__ __forceinline__ void mma16816(float* d, const uint32_t* a,
                                         const uint32_t* b) {
    asm volatile(
        "mma.sync.aligned.m16n8k16.row.col.f32.bf16.bf16.f32 "
        "{%0,%1,%2,%3}, {%4,%5,%6,%7}, {%8,%9}, {%0,%1,%2,%3};"
        : "+f"(d[0]), "+f"(d[1]), "+f"(d[2]), "+f"(d[3])
        : "r"(a[0]), "r"(a[1]), "r"(a[2]), "r"(a[3]), "r"(b[0]), "r"(b[1]));
}

// ---------------------------------------------------------------------------
// Prep: in = 128x128 fp32 [k rows][m cols]  ->  out tile = transposed [m][k]
// bf16, hi plane then lo plane, row stride RS ushorts.
// ---------------------------------------------------------------------------
__global__ __launch_bounds__(256) void prep_kernel(const float* __restrict__ in,
                                                   uint8_t* __restrict__ out) {
    extern __shared__ float stage[];  // [128][129]
    const int tid = threadIdx.x;
    const float* inp = in + (size_t)blockIdx.x * 16384;
    uint8_t* outp = out + (size_t)blockIdx.x * TILE;

    for (int i = tid; i < 4096; i += 256) {
        int row = i >> 5, c4 = (i & 31) * 4;
        float4 v = *(const float4*)&inp[row * 128 + c4];
        float* sr = &stage[row * 129 + c4];
        sr[0] = v.x; sr[1] = v.y; sr[2] = v.z; sr[3] = v.w;
    }
    __syncthreads();
    for (int it = tid; it < 2048; it += 256) {
        int m = it >> 4, kc = it & 15;       // 8 consecutive k per thread
        uint32_t hw[4], lw[4];
#pragma unroll
        for (int u = 0; u < 4; ++u) {
            float v0 = stage[(kc * 8 + 2 * u) * 129 + m];
            float v1 = stage[(kc * 8 + 2 * u + 1) * 129 + m];
            __nv_bfloat16 h0 = __float2bfloat16(v0), h1 = __float2bfloat16(v1);
            __nv_bfloat16 l0 = __float2bfloat16(v0 - __bfloat162float(h0));
            __nv_bfloat16 l1 = __float2bfloat16(v1 - __bfloat162float(h1));
            hw[u] = (uint32_t)__bfloat16_as_ushort(h0) |
                    ((uint32_t)__bfloat16_as_ushort(h1) << 16);
            lw[u] = (uint32_t)__bfloat16_as_ushort(l0) |
                    ((uint32_t)__bfloat16_as_ushort(l1) << 16);
        }
        uint32_t off = (uint32_t)m * (RS * 2) + (uint32_t)kc * 16;
        *(uint4*)(outp + off)         = make_uint4(hw[0], hw[1], hw[2], hw[3]);
        *(uint4*)(outp + PLANE + off) = make_uint4(lw[0], lw[1], lw[2], lw[3]);
    }
}

// ---------------------------------------------------------------------------
// Mix: block = (b, strip); handles j = strip + 16*i, i = 0..7.
//   Y[h,t] = sum_s X[b,s,h]*W1[j,s,t] ; res[h] = sum_t gelu(Y+b1)*W2
//   out[b,j,h] = base[b,j,h] + res[h] + b2[j]
// ---------------------------------------------------------------------------
#define SM_X   0
#define SM_A0  69632
#define SM_A1  139264
#define SM_RED 208896            // 128*17 floats = 8704 B
#define SM_MB  217600
#define SMEM_MIX 217632

__global__ __launch_bounds__(256, 1) void mix_kernel(
    const uint8_t* __restrict__ Xt, const uint8_t* __restrict__ At,
    const float* __restrict__ b1g, const float* __restrict__ w2g,
    const float* __restrict__ b2g, const float* __restrict__ baseg,
    float* __restrict__ outg)
{
    extern __shared__ __align__(16) uint8_t smem[];
    const uint32_t sb = s2u(smem);
    const int tid = threadIdx.x;
    const int wid = tid >> 5, lane = tid & 31;
    const int g = lane >> 2, q = lane & 3;
    const int wm = wid >> 2, wn = wid & 3;      // warp grid 2(M) x 4(N)
    const int b = blockIdx.x >> 4, strip = blockIdx.x & 15;

    const uint32_t mb0 = sb + SM_MB, mb1 = sb + SM_MB + 8;

    // zero both A buffers once (rows > j must be exact zeros)
    {
        uint4 z = make_uint4(0, 0, 0, 0);
        uint4* p = (uint4*)(smem + SM_A0);
        for (int i = tid; i < (2 * TILE) / 16; i += 256) p[i] = z;
    }
    __syncthreads();
    if (tid == 0) {
        mbar_init(mb0, 1); mbar_init(mb1, 1);
        asm volatile("fence.proxy.async.shared::cta;" ::: "memory");
        // X + A(i=0) on mb0
        int j0 = strip;
        uint32_t rA0 = (uint32_t)(j0 + 1) * 272;
        mbar_expect(mb0, (uint32_t)TILE + 2 * rA0);
        bulk_g2s(sb + SM_X, Xt + (size_t)b * TILE, TILE, mb0);
        const uint8_t* a0 = At + (size_t)j0 * TILE;
        bulk_g2s(sb + SM_A0, a0, rA0, mb0);
        bulk_g2s(sb + SM_A0 + PLANE, a0 + PLANE, rA0, mb0);
        // A(i=1) on mb1
        int j1 = strip + 16;
        uint32_t rA1 = (uint32_t)(j1 + 1) * 272;
        mbar_expect(mb1, 2 * rA1);
        const uint8_t* a1 = At + (size_t)j1 * TILE;
        bulk_g2s(sb + SM_A1, a1, rA1, mb1);
        bulk_g2s(sb + SM_A1 + PLANE, a1 + PLANE, rA1, mb1);
    }
    __syncthreads();

    const uint16_t* Xh = (const uint16_t*)(smem + SM_X);
    const uint16_t* Xl = (const uint16_t*)(smem + SM_X + PLANE);
    float* red = (float*)(smem + SM_RED);

    int phL[2] = {0, 0};

    for (int i = 0; i < NJ; ++i) {
        const int buf = i & 1;
        const int j = strip + 16 * i;
        const uint32_t abase = buf ? SM_A1 : SM_A0;
        const uint16_t* Ah = (const uint16_t*)(smem + abase);
        const uint16_t* Al = (const uint16_t*)(smem + abase + PLANE);

        mbar_wait(buf ? mb1 : mb0, phL[buf]); phL[buf] ^= 1;

        float d[4][4][4];
#pragma unroll
        for (int mt = 0; mt < 4; ++mt)
#pragma unroll
            for (int nt = 0; nt < 4; ++nt)
#pragma unroll
                for (int c = 0; c < 4; ++c) d[mt][nt][c] = 0.0f;

        const bool wact = (wn * 32) <= j;
        if (wact) {
            const int nc = (j >> 4) + 1;
            for (int kc = 0; kc < nc; ++kc) {
                const int c0 = kc * 16 + 2 * q;
                uint32_t bh[4][2], bl[4][2];
#pragma unroll
                for (int nt = 0; nt < 4; ++nt) {
                    if (wn * 32 + nt * 8 <= j) {
                        int row = (wn * 32 + nt * 8 + g) * RS;
                        bh[nt][0] = *(const uint32_t*)&Ah[row + c0];
                        bh[nt][1] = *(const uint32_t*)&Ah[row + c0 + 8];
                        bl[nt][0] = *(const uint32_t*)&Al[row + c0];
                        bl[nt][1] = *(const uint32_t*)&Al[row + c0 + 8];
                    }
                }
#pragma unroll
                for (int mt = 0; mt < 4; ++mt) {
                    int r0 = (wm * 64 + mt * 16 + g) * RS;
                    int r1 = r0 + 8 * RS;
                    uint32_t ah[4], al[4];
                    ah[0] = *(const uint32_t*)&Xh[r0 + c0];
                    ah[1] = *(const uint32_t*)&Xh[r1 + c0];
                    ah[2] = *(const uint32_t*)&Xh[r0 + c0 + 8];
                    ah[3] = *(const uint32_t*)&Xh[r1 + c0 + 8];
                    al[0] = *(const uint32_t*)&Xl[r0 + c0];
                    al[1] = *(const uint32_t*)&Xl[r1 + c0];
                    al[2] = *(const uint32_t*)&Xl[r0 + c0 + 8];
                    al[3] = *(const uint32_t*)&Xl[r1 + c0 + 8];
#pragma unroll
                    for (int nt = 0; nt < 4; ++nt) {
                        if (wn * 32 + nt * 8 <= j) {
                            mma16816(d[mt][nt], ah, bh[nt]);
                            mma16816(d[mt][nt], ah, bl[nt]);
                            mma16816(d[mt][nt], al, bh[nt]);
                        }
                    }
                }
            }
        }
        __syncthreads();   // all warps done reading A[buf]

        if (tid == 0 && i + 2 < NJ) {
            int jn = strip + 16 * (i + 2);
            uint32_t rA = (uint32_t)(jn + 1) * 272;
            uint32_t mb = buf ? mb1 : mb0;
            mbar_expect(mb, 2 * rA);
            const uint8_t* an = At + (size_t)jn * TILE;
            bulk_g2s(sb + abase, an, rA, mb);
            bulk_g2s(sb + abase + PLANE, an + PLANE, rA, mb);
        }

        // ---- epilogue: res[h] = sum_t gelu(Y+b1[t])*W2[t] ----
        float p[8];
#pragma unroll
        for (int r = 0; r < 8; ++r) p[r] = 0.0f;
        if (wact) {
#pragma unroll
            for (int nt = 0; nt < 4; ++nt) {
                int tcol = wn * 32 + nt * 8 + 2 * q;
                if (wn * 32 + nt * 8 <= j) {
                    float b1a = b1g[j * 128 + tcol], b1b = b1g[j * 128 + tcol + 1];
                    float w2a = w2g[j * 128 + tcol], w2b = w2g[j * 128 + tcol + 1];
#pragma unroll
                    for (int mt = 0; mt < 4; ++mt) {
#pragma unroll
                        for (int gg = 0; gg < 2; ++gg) {
                            float y0 = d[mt][nt][gg * 2 + 0] + b1a;
                            float y1 = d[mt][nt][gg * 2 + 1] + b1b;
                            p[mt * 2 + gg] += gelu_f(y0) * w2a + gelu_f(y1) * w2b;
                        }
                    }
                }
            }
        }
#pragma unroll
        for (int mt = 0; mt < 4; ++mt)
#pragma unroll
            for (int gg = 0; gg < 2; ++gg) {
                int h = wm * 64 + mt * 16 + g + gg * 8;
                red[h * 17 + wn * 4 + q] = p[mt * 2 + gg];
            }
        __syncthreads();
        if (tid < 128) {
            float s = 0.0f;
#pragma unroll
            for (int c = 0; c < 16; ++c) s += red[tid * 17 + c];
            size_t o = ((size_t)b * 128 + j) * 128 + tid;
            outg[o] = baseg[o] + b2g[j] + s;
        }
        __syncthreads();
    }
}

// ---------------------------------------------------------------------------
// MLP GEMM (FFMA2, unchanged — passes at rel_err 2e-7)
// ---------------------------------------------------------------------------
__global__ __launch_bounds__(256) void mlp_kernel(
    const float* __restrict__ in, const float* __restrict__ W,
    const float* __restrict__ bias, float* __restrict__ out, int act)
{
    __shared__ __align__(16) float Ins[16][33];
    __shared__ __align__(16) float Ws[16][128];
    const int tid = threadIdx.x;
    const int cx = tid & 15, ry = tid >> 4;
    const int c0 = cx * 8, r0g = blockIdx.x * 32;

    unsigned long long acc[2][4];
#pragma unroll
    for (int r = 0; r < 2; ++r)
#pragma unroll
        for (int c = 0; c < 4; ++c) acc[r][c] = 0ull;

    for (int k0 = 0; k0 < 128; k0 += 16) {
        __syncthreads();
        if (tid < 128) {
            int row = tid >> 2, q4 = (tid & 3) * 4;
            float4 v = *(const float4*)&in[(r0g + row) * 128 + k0 + q4];
            Ins[q4 + 0][row] = v.x; Ins[q4 + 1][row] = v.y;
            Ins[q4 + 2][row] = v.z; Ins[q4 + 3][row] = v.w;
        }
        {
            int i = tid;
#pragma unroll
            for (int rp = 0; rp < 2; ++rp, i += 256) {
                int row = i >> 5, c4 = (i & 31) * 4;
                *(float4*)&Ws[row][c4] = *(const float4*)&W[(k0 + row) * 128 + c4];
            }
        }
        __syncthreads();
#pragma unroll
        for (int kk = 0; kk < 16; ++kk) {
            unsigned long long ad0 = dup2(Ins[kk][ry * 2]);
            unsigned long long ad1 = dup2(Ins[kk][ry * 2 + 1]);
            ulonglong2 bv0 = *(const ulonglong2*)&Ws[kk][c0];
            ulonglong2 bv1 = *(const ulonglong2*)&Ws[kk][c0 + 4];
            fma2(acc[0][0], ad0, bv0.x); fma2(acc[0][1], ad0, bv0.y);
            fma2(acc[0][2], ad0, bv1.x); fma2(acc[0][3], ad0, bv1.y);
            fma2(acc[1][0], ad1, bv0.x); fma2(acc[1][1], ad1, bv0.y);
            fma2(acc[1][2], ad1, bv1.x); fma2(acc[1][3], ad1, bv1.y);
        }
    }
#pragma unroll
    for (int r = 0; r < 2; ++r) {
        int row = r0g + ry * 2 + r;
        float o[8];
#pragma unroll
        for (int c = 0; c < 8; ++c) {
            unsigned long long v = acc[r][c >> 1];
            float y = ((c & 1) ? hi32(v) : lo32(v)) + bias[c0 + c];
            o[c] = act ? gelu_f(y) : y;
        }
        *(float4*)&out[row * 128 + c0]     = make_float4(o[0], o[1], o[2], o[3]);
        *(float4*)&out[row * 128 + c0 + 4] = make_float4(o[4], o[5], o[6], o[7]);
    }
}

__global__ void copy_kernel(const float4* __restrict__ src,
                            float4* __restrict__ dst, int n4) {
    int i = blockIdx.x * blockDim.x + threadIdx.x;
    if (i < n4) dst[i] = src[i];
}

// ---------------------------------------------------------------------------
extern "C" void kernel_launch(void* const* d_in, const int* in_sizes, int n_in,
                              void* d_out, int out_size)
{
    const float* trend0 = (const float*)d_in[0];
    const float* trend1 = (const float*)d_in[1];
    const float* trend2 = (const float*)d_in[2];
    const float* W1  = (const float*)d_in[3];
    const float* b1  = (const float*)d_in[4];
    const float* W2  = (const float*)d_in[5];
    const float* b2  = (const float*)d_in[6];
    const float* Wm1 = (const float*)d_in[7];
    const float* bm1 = (const float*)d_in[8];
    const float* Wm2 = (const float*)d_in[9];
    const float* bm2 = (const float*)d_in[10];

    float* out = (float*)d_out;
    float* O0 = out;
    float* O1 = out + BSH;
    float* O2 = out + 2 * BSH;

    float *pM, *pT;
    uint8_t *pA, *pB;
    cudaGetSymbolAddress((void**)&pM, g_M);
    cudaGetSymbolAddress((void**)&pT, g_T);
    cudaGetSymbolAddress((void**)&pA, g_A);
    cudaGetSymbolAddress((void**)&pB, g_B);

    cudaFuncSetAttribute(mix_kernel, cudaFuncAttributeMaxDynamicSharedMemorySize, SMEM_MIX);
    cudaFuncSetAttribute(prep_kernel, cudaFuncAttributeMaxDynamicSharedMemorySize, 66048);

    // prep A (both scales, 256 tiles) and B(trend2)
    prep_kernel<<<256, 256, 66048>>>(W1, pA);
    prep_kernel<<<32, 256, 66048>>>(trend2, pB);

    // scale 0: res = mix(trend2); O1 = mlp(trend1 + res)
    mix_kernel<<<512, 256, SMEM_MIX>>>(pB, pA, b1, W2, b2, trend1, pM);
    mlp_kernel<<<128, 256>>>(pM, Wm1, bm1, pT, 1);
    mlp_kernel<<<128, 256>>>(pT, Wm2, bm2, O1, 0);

    // scale 1: res = mix(O1); O0 = mlp(trend0 + res)
    prep_kernel<<<32, 256, 66048>>>(O1, pB);
    mix_kernel<<<512, 256, SMEM_MIX>>>(pB, pA + (size_t)128 * TILE,
                                       b1 + Sc * Sc, W2 + Sc * Sc, b2 + Sc,
                                       trend0, pM);
    mlp_kernel<<<128, 256>>>(pM, Wm1, bm1, pT, 1);
    mlp_kernel<<<128, 256>>>(pT, Wm2, bm2, O0, 0);

    copy_kernel<<<BSH / 4 / 256, 256>>>((const float4*)trend2, (float4*)O2, BSH / 4);
}

// round 5
// speedup vs baseline: 1.3990x; 1.3990x over previous
#include <cuda_runtime.h>
#include <stdint.h>

#define Bc 32
#define Sc 128
#define Hc 128
#define BSH (Bc * Sc * Hc)

__device__ float g_M[BSH];
__device__ float g_T[BSH];

// ---------------------------------------------------------------------------
__device__ __forceinline__ float gelu_f(float x) {
    return 0.5f * x * (1.0f + erff(x * 0.7071067811865476f));
}
__device__ __forceinline__ unsigned long long dup2(float x) {
    unsigned long long r; unsigned int u = __float_as_uint(x);
    asm("mov.b64 %0, {%1, %1};" : "=l"(r) : "r"(u)); return r;
}
__device__ __forceinline__ void fma2(unsigned long long &d, unsigned long long a,
                                     unsigned long long b) {
    asm("fma.rn.f32x2 %0, %1, %2, %3;" : "=l"(d) : "l"(a), "l"(b), "l"(d));
}
__device__ __forceinline__ float lo32(unsigned long long v) {
    return __uint_as_float((unsigned int)v);
}
__device__ __forceinline__ float hi32(unsigned long long v) {
    return __uint_as_float((unsigned int)(v >> 32));
}
__device__ __forceinline__ uint32_t s2u(const void* p) {
    uint32_t a;
    asm("{ .reg .u64 t; cvta.to.shared.u64 t, %1; cvt.u32.u64 %0, t; }" : "=r"(a) : "l"(p));
    return a;
}
__device__ __forceinline__ void cpasync16(uint32_t dst, const void* src) {
    asm volatile("cp.async.ca.shared.global [%0], [%1], 16;" :: "r"(dst), "l"(src));
}
#define CP_COMMIT() asm volatile("cp.async.commit_group;" ::: "memory")
#define CP_WAIT1()  asm volatile("cp.async.wait_group 1;" ::: "memory")

// ---------------------------------------------------------------------------
// Mix kernel: one block per (b, j).  cp.async double-buffered K pipeline.
//   Y[h,t] = sum_s X[b,s,h] * W1[j,s,t]  (ragged K: s <= j, zero-masked)
//   res[h] = sum_t gelu(Y[h,t]+b1[j,t]) * W2[j,t]
//   out[b,j,h] = base[b,j,h] + res[h] + b2[j]
// ---------------------------------------------------------------------------
__device__ __forceinline__ void mix_issue(const float* __restrict__ Xg,
                                          const float* __restrict__ Wg,
                                          uint32_t xsb, uint32_t wsb,
                                          int c, int buf, int tid) {
    const int k0 = c * 16;
#pragma unroll
    for (int p = 0; p < 2; ++p) {
        int idx = tid + p * 256;
        int row = idx >> 5, colf = (idx & 31) * 4;
        uint32_t off = (uint32_t)(buf * 2048 + row * 128 + colf) * 4;
        cpasync16(xsb + off, Xg + (k0 + row) * 128 + colf);
        cpasync16(wsb + off, Wg + (k0 + row) * 128 + colf);
    }
}

__global__ __launch_bounds__(256, 2) void mix_kernel(
    const float* __restrict__ X,     // [B,S,H]
    const float* __restrict__ W1,    // [S,S,S] (this scale)
    const float* __restrict__ b1,    // [S,S]
    const float* __restrict__ W2,    // [S,S]
    const float* __restrict__ b2,    // [S]
    const float* __restrict__ base,  // [B,S,H]
    float* __restrict__ out)         // [B,S,H]
{
    __shared__ __align__(16) float Xs[2][16][Hc];
    __shared__ __align__(16) float Ws[2][16][Sc];
    __shared__ __align__(16) float red[16][Hc + 1];

    const int b  = blockIdx.x & 31;
    const int j  = blockIdx.x >> 5;
    const int nc = (j >> 4) + 1;

    const int tid = threadIdx.x;
    const int tx  = tid >> 4;   // t-tile 0..15
    const int ty  = tid & 15;   // h-tile 0..15
    const int t0  = tx * 8;
    const int h0  = ty * 8;
    const int w   = tid >> 5;
    const bool wact = (w * 16) <= j;

    const float* Xg  = X  + (long)b * Sc * Hc;
    const float* W1g = W1 + (long)j * Sc * Sc;
    const uint32_t xsb = s2u(Xs), wsb = s2u(Ws);

    unsigned long long acc[8][4];
#pragma unroll
    for (int r = 0; r < 8; ++r)
#pragma unroll
        for (int c = 0; c < 4; ++c) acc[r][c] = 0ull;

    // 2-stage prologue
    mix_issue(Xg, W1g, xsb, wsb, 0, 0, tid);
    CP_COMMIT();
    if (nc > 1) mix_issue(Xg, W1g, xsb, wsb, 1, 1, tid);
    CP_COMMIT();

    for (int c = 0; c < nc; ++c) {
        CP_WAIT1();
        __syncthreads();
        const int buf = c & 1;
        if (wact) {
#pragma unroll
            for (int kk = 0; kk < 16; ++kk) {
                float4 a0 = *(const float4*)&Xs[buf][kk][h0];
                float4 a1 = *(const float4*)&Xs[buf][kk][h0 + 4];
                ulonglong2 bv0 = *(const ulonglong2*)&Ws[buf][kk][t0];
                ulonglong2 bv1 = *(const ulonglong2*)&Ws[buf][kk][t0 + 4];
                unsigned long long bb0 = bv0.x, bb1 = bv0.y;
                unsigned long long bb2 = bv1.x, bb3 = bv1.y;
                float av[8] = {a0.x, a0.y, a0.z, a0.w, a1.x, a1.y, a1.z, a1.w};
#pragma unroll
                for (int r = 0; r < 8; ++r) {
                    unsigned long long ad = dup2(av[r]);
                    fma2(acc[r][0], ad, bb0);
                    fma2(acc[r][1], ad, bb1);
                    fma2(acc[r][2], ad, bb2);
                    fma2(acc[r][3], ad, bb3);
                }
            }
        }
        __syncthreads();
        if (c + 2 < nc) mix_issue(Xg, W1g, xsb, wsb, c + 2, buf, tid);
        CP_COMMIT();
    }

    // Epilogue: partial row-reductions over this thread's 8 t-columns
    float part[8];
#pragma unroll
    for (int r = 0; r < 8; ++r) part[r] = 0.0f;

    if (wact) {
#pragma unroll
        for (int c = 0; c < 8; ++c) {
            int t = t0 + c;
            float w2v = W2[j * Sc + t];
            float b1v = b1[j * Sc + t];
#pragma unroll
            for (int r = 0; r < 8; ++r) {
                unsigned long long v = acc[r][c >> 1];
                float y = ((c & 1) ? hi32(v) : lo32(v)) + b1v;
                part[r] += gelu_f(y) * w2v;
            }
        }
    }

#pragma unroll
    for (int r = 0; r < 8; ++r) red[tx][h0 + r] = part[r];
    __syncthreads();

    if (tid < Hc) {
        int h = tid;
        float s = base[((long)b * Sc + j) * Hc + h] + b2[j];
#pragma unroll
        for (int q = 0; q < 16; ++q) s += red[q][h];
        out[((long)b * Sc + j) * Hc + h] = s;
    }
}

// ---------------------------------------------------------------------------
// MLP GEMM: out[r,c] = act( sum_k in[r,k]*W[k,c] + bias[c] )
// 256 blocks x 16 rows; cp.async double-buffered K pipeline.
// Thread: 1 row x 8 cols (FFMA2 col pairs).
// ---------------------------------------------------------------------------
__device__ __forceinline__ void mlp_issue(const float* __restrict__ in,
                                          const float* __restrict__ W,
                                          uint32_t insb, uint32_t wsb,
                                          int r0g, int c, int buf, int tid) {
    const int k0 = c * 16;
    if (tid < 64) {   // Ins: 16 rows x 16 k-floats
        int row = tid >> 2, colf = (tid & 3) * 4;
        cpasync16(insb + (uint32_t)(buf * 256 + row * 16 + colf) * 4,
                  in + (r0g + row) * 128 + k0 + colf);
    }
#pragma unroll
    for (int p = 0; p < 2; ++p) {   // Ws: 16 k-rows x 128 cols
        int idx = tid + p * 256;
        int row = idx >> 5, colf = (idx & 31) * 4;
        cpasync16(wsb + (uint32_t)(buf * 2048 + row * 128 + colf) * 4,
                  W + (k0 + row) * 128 + colf);
    }
}

__global__ __launch_bounds__(256) void mlp_kernel(
    const float* __restrict__ in,    // [4096,128]
    const float* __restrict__ W,     // [128,128] (in,out)
    const float* __restrict__ bias,  // [128]
    float* __restrict__ out,         // [4096,128]
    int act)
{
    __shared__ __align__(16) float Ins[2][16][16];   // [buf][row][k]
    __shared__ __align__(16) float Ws[2][16][128];   // [buf][k][col]

    const int tid = threadIdx.x;
    const int cx  = tid & 15, ry = tid >> 4;
    const int c0  = cx * 8;
    const int r0g = blockIdx.x * 16;
    const uint32_t insb = s2u(Ins), wsb = s2u(Ws);

    unsigned long long acc[4];
#pragma unroll
    for (int c = 0; c < 4; ++c) acc[c] = 0ull;

    mlp_issue(in, W, insb, wsb, r0g, 0, 0, tid);
    CP_COMMIT();
    mlp_issue(in, W, insb, wsb, r0g, 1, 1, tid);
    CP_COMMIT();

    for (int c = 0; c < 8; ++c) {
        CP_WAIT1();
        __syncthreads();
        const int buf = c & 1;
#pragma unroll
        for (int kk = 0; kk < 16; ++kk) {
            unsigned long long ad = dup2(Ins[buf][ry][kk]);
            ulonglong2 bv0 = *(const ulonglong2*)&Ws[buf][kk][c0];
            ulonglong2 bv1 = *(const ulonglong2*)&Ws[buf][kk][c0 + 4];
            fma2(acc[0], ad, bv0.x); fma2(acc[1], ad, bv0.y);
            fma2(acc[2], ad, bv1.x); fma2(acc[3], ad, bv1.y);
        }
        __syncthreads();
        if (c + 2 < 8) mlp_issue(in, W, insb, wsb, r0g, c + 2, buf, tid);
        CP_COMMIT();
    }

    int row = r0g + ry;
    float o[8];
#pragma unroll
    for (int c = 0; c < 8; ++c) {
        unsigned long long v = acc[c >> 1];
        float y = ((c & 1) ? hi32(v) : lo32(v)) + bias[c0 + c];
        o[c] = act ? gelu_f(y) : y;
    }
    *(float4*)&out[row * 128 + c0]     = make_float4(o[0], o[1], o[2], o[3]);
    *(float4*)&out[row * 128 + c0 + 4] = make_float4(o[4], o[5], o[6], o[7]);
}

// ---------------------------------------------------------------------------
__global__ void copy_kernel(const float4* __restrict__ src,
                            float4* __restrict__ dst, int n4)
{
    int i = blockIdx.x * blockDim.x + threadIdx.x;
    if (i < n4) dst[i] = src[i];
}

// ---------------------------------------------------------------------------
extern "C" void kernel_launch(void* const* d_in, const int* in_sizes, int n_in,
                              void* d_out, int out_size)
{
    const float* trend0 = (const float*)d_in[0];
    const float* trend1 = (const float*)d_in[1];
    const float* trend2 = (const float*)d_in[2];
    const float* W1     = (const float*)d_in[3];
    const float* b1     = (const float*)d_in[4];
    const float* W2     = (const float*)d_in[5];
    const float* b2     = (const float*)d_in[6];
    const float* Wm1    = (const float*)d_in[7];
    const float* bm1    = (const float*)d_in[8];
    const float* Wm2    = (const float*)d_in[9];
    const float* bm2    = (const float*)d_in[10];

    float* out = (float*)d_out;
    float* O0 = out;             // mlp(trend0 + res1)
    float* O1 = out + BSH;       // mlp(trend1 + res0)
    float* O2 = out + 2 * BSH;   // trend2

    float *pM, *pT;
    cudaGetSymbolAddress((void**)&pM, g_M);
    cudaGetSymbolAddress((void**)&pT, g_T);

    dim3 blk(256);
    dim3 mixGrid(Bc * Sc);    // 4096 blocks, b fastest (W1[j] L2 reuse)
    dim3 mlpGrid(256);        // 16 rows per block

    // scale i=0: X = trend2, base = trend1 -> O1 = mlp(M0)
    mix_kernel<<<mixGrid, blk>>>(trend2, W1, b1, W2, b2, trend1, pM);
    mlp_kernel<<<mlpGrid, blk>>>(pM, Wm1, bm1, pT, 1);
    mlp_kernel<<<mlpGrid, blk>>>(pT, Wm2, bm2, O1, 0);

    // scale i=1: X = O1, base = trend0 -> O0 = mlp(M1)
    mix_kernel<<<mixGrid, blk>>>(O1, W1 + Sc * Sc * Sc, b1 + Sc * Sc,
                                 W2 + Sc * Sc, b2 + Sc, trend0, pM);
    mlp_kernel<<<mlpGrid, blk>>>(pM, Wm1, bm1, pT, 1);
    mlp_kernel<<<mlpGrid, blk>>>(pT, Wm2, bm2, O0, 0);

    // out2 = trend2
    copy_kernel<<<BSH / 4 / 256, 256>>>((const float4*)trend2, (float4*)O2,
                                        BSH / 4);
}